// round 1
// baseline (speedup 1.0000x reference)
#include <cuda_runtime.h>
#include <math.h>

// Problem constants
#define B_  8
#define C_  512
#define T_  4096
#define G_  32
#define CPG (C_ / G_)   // 16

// Scratch (device globals — allocation-free rule)
__device__ float g_h  [(size_t)B_ * C_ * T_];           //  67 MB  groupnorm output
__device__ float g_qkv[(size_t)B_ * 3 * C_ * T_];       // 201 MB  qkv
__device__ float g_s  [(size_t)B_ * T_ * T_];           // 536 MB  attention scores
__device__ float g_ao [(size_t)B_ * C_ * T_];           //  67 MB  attn @ V

// ---------------------------------------------------------------------------
// GroupNorm: one block per (batch, group). 16 ch * 4096 = 65536 elems/block.
// ---------------------------------------------------------------------------
__global__ __launch_bounds__(256) void gn_kernel(const float* __restrict__ x,
                                                 const float* __restrict__ w,
                                                 const float* __restrict__ b,
                                                 float* __restrict__ h) {
    const int bg = blockIdx.x;
    const int bb = bg >> 5;        // / 32
    const int g  = bg & 31;
    const size_t base = ((size_t)bb * C_ + (size_t)g * CPG) * T_;
    const float4* xp4 = reinterpret_cast<const float4*>(x + base);
    const int n4 = CPG * T_ / 4;   // 16384 float4
    float s = 0.f, s2 = 0.f;
    for (int i = threadIdx.x; i < n4; i += 256) {
        float4 v = xp4[i];
        s  += v.x + v.y + v.z + v.w;
        s2 += v.x * v.x + v.y * v.y + v.z * v.z + v.w * v.w;
    }
    __shared__ float rs[256], rq[256];
    rs[threadIdx.x] = s; rq[threadIdx.x] = s2;
    __syncthreads();
    for (int off = 128; off > 0; off >>= 1) {
        if (threadIdx.x < off) {
            rs[threadIdx.x] += rs[threadIdx.x + off];
            rq[threadIdx.x] += rq[threadIdx.x + off];
        }
        __syncthreads();
    }
    const float inv_n = 1.0f / (float)(CPG * T_);
    const float mean  = rs[0] * inv_n;
    const float var   = rq[0] * inv_n - mean * mean;
    const float rstd  = rsqrtf(var + 1e-5f);
    float4* hp4 = reinterpret_cast<float4*>(h + base);
    for (int i = threadIdx.x; i < n4; i += 256) {
        int c = g * CPG + (i * 4) / T_;     // T_ % 4 == 0, no straddle
        float sc = w[c] * rstd;
        float sh = b[c] - mean * sc;
        float4 v = xp4[i];
        v.x = v.x * sc + sh;
        v.y = v.y * sc + sh;
        v.z = v.z * sc + sh;
        v.w = v.w * sc + sh;
        hp4[i] = v;
    }
}

// ---------------------------------------------------------------------------
// Tiled FP32 GEMM: C[m,n] = alpha * sum_k A(k,m) * B(k,n)  (+bias[m] +res[m,n])
//   A_KMAJOR: A[k*lda + m]  else A[m*lda + k]
//   B_KMAJOR: B[k*ldb + n]  else B[n*ldb + k]
// BM=BN=128, BK=16, 256 threads, 8x8 per-thread microtile.
// All dims assumed divisible by tile sizes (true for this problem).
// ---------------------------------------------------------------------------
template<bool A_KMAJOR, bool B_KMAJOR>
__global__ __launch_bounds__(256) void gemm_kernel(
    const float* __restrict__ A, const float* __restrict__ Bm,
    float* __restrict__ C,
    const float* __restrict__ bias, const float* __restrict__ res,
    int M, int N, int K, int lda, int ldb, int ldc,
    size_t sA, size_t sB, size_t sC, size_t sR, float alpha)
{
    constexpr int BK = 16;
    __shared__ float As[BK][128];
    __shared__ float Bs[BK][128];

    const int z = blockIdx.z;
    A  += sA * (size_t)z;
    Bm += sB * (size_t)z;
    C  += sC * (size_t)z;
    if (res) res += sR * (size_t)z;

    const int m0 = blockIdx.y * 128;
    const int n0 = blockIdx.x * 128;
    const int tid = threadIdx.x;
    const int tx = tid & 15;       // n sub
    const int ty = tid >> 4;       // m sub

    float acc[8][8];
    #pragma unroll
    for (int i = 0; i < 8; ++i)
        #pragma unroll
        for (int j = 0; j < 8; ++j) acc[i][j] = 0.f;

    for (int k0 = 0; k0 < K; k0 += BK) {
        // ---- load A tile ----
        if (A_KMAJOR) {
            #pragma unroll
            for (int r = 0; r < 2; ++r) {
                int q  = tid + 256 * r;          // 0..511 float4 chunks
                int kk = q >> 5;                 // (q*4)/128
                int mm = (q & 31) * 4;
                float4 v = *reinterpret_cast<const float4*>(
                    A + (size_t)(k0 + kk) * lda + m0 + mm);
                *reinterpret_cast<float4*>(&As[kk][mm]) = v;
            }
        } else {
            #pragma unroll
            for (int r = 0; r < 2; ++r) {
                int q   = tid + 256 * r;
                int row = q >> 2;                // 0..127
                int kc  = (q & 3) * 4;
                float4 v = *reinterpret_cast<const float4*>(
                    A + (size_t)(m0 + row) * lda + k0 + kc);
                As[kc + 0][row] = v.x;
                As[kc + 1][row] = v.y;
                As[kc + 2][row] = v.z;
                As[kc + 3][row] = v.w;
            }
        }
        // ---- load B tile ----
        if (B_KMAJOR) {
            #pragma unroll
            for (int r = 0; r < 2; ++r) {
                int q  = tid + 256 * r;
                int kk = q >> 5;
                int nn = (q & 31) * 4;
                float4 v = *reinterpret_cast<const float4*>(
                    Bm + (size_t)(k0 + kk) * ldb + n0 + nn);
                *reinterpret_cast<float4*>(&Bs[kk][nn]) = v;
            }
        } else {
            #pragma unroll
            for (int r = 0; r < 2; ++r) {
                int q   = tid + 256 * r;
                int row = q >> 2;
                int kc  = (q & 3) * 4;
                float4 v = *reinterpret_cast<const float4*>(
                    Bm + (size_t)(n0 + row) * ldb + k0 + kc);
                Bs[kc + 0][row] = v.x;
                Bs[kc + 1][row] = v.y;
                Bs[kc + 2][row] = v.z;
                Bs[kc + 3][row] = v.w;
            }
        }
        __syncthreads();

        #pragma unroll
        for (int kk = 0; kk < BK; ++kk) {
            float a[8], bfr[8];
            *reinterpret_cast<float4*>(a)       = *reinterpret_cast<float4*>(&As[kk][ty * 8]);
            *reinterpret_cast<float4*>(a + 4)   = *reinterpret_cast<float4*>(&As[kk][ty * 8 + 4]);
            *reinterpret_cast<float4*>(bfr)     = *reinterpret_cast<float4*>(&Bs[kk][tx * 8]);
            *reinterpret_cast<float4*>(bfr + 4) = *reinterpret_cast<float4*>(&Bs[kk][tx * 8 + 4]);
            #pragma unroll
            for (int i = 0; i < 8; ++i)
                #pragma unroll
                for (int j = 0; j < 8; ++j)
                    acc[i][j] += a[i] * bfr[j];
        }
        __syncthreads();
    }

    // ---- epilogue ----
    #pragma unroll
    for (int i = 0; i < 8; ++i) {
        int m = m0 + ty * 8 + i;
        float bv = bias ? bias[m] : 0.f;
        #pragma unroll
        for (int j = 0; j < 8; j += 4) {
            int n = n0 + tx * 8 + j;
            size_t idx = (size_t)m * ldc + n;
            float4 v;
            v.x = alpha * acc[i][j + 0] + bv;
            v.y = alpha * acc[i][j + 1] + bv;
            v.z = alpha * acc[i][j + 2] + bv;
            v.w = alpha * acc[i][j + 3] + bv;
            if (res) {
                float4 rv = *reinterpret_cast<const float4*>(res + idx);
                v.x += rv.x; v.y += rv.y; v.z += rv.z; v.w += rv.w;
            }
            *reinterpret_cast<float4*>(C + idx) = v;
        }
    }
}

// ---------------------------------------------------------------------------
// Row softmax over 4096 cols; one block (256 thr) per row, row in registers.
// ---------------------------------------------------------------------------
__global__ __launch_bounds__(256) void softmax_kernel(float* __restrict__ s) {
    float4* p = reinterpret_cast<float4*>(s + (size_t)blockIdx.x * T_);
    const int tid = threadIdx.x;
    float4 v[4];
    float mx = -1e30f;
    #pragma unroll
    for (int r = 0; r < 4; ++r) {
        v[r] = p[tid + 256 * r];
        mx = fmaxf(mx, fmaxf(fmaxf(v[r].x, v[r].y), fmaxf(v[r].z, v[r].w)));
    }
    __shared__ float red[256];
    red[tid] = mx;
    __syncthreads();
    for (int off = 128; off > 0; off >>= 1) {
        if (tid < off) red[tid] = fmaxf(red[tid], red[tid + off]);
        __syncthreads();
    }
    mx = red[0];
    __syncthreads();
    float sum = 0.f;
    #pragma unroll
    for (int r = 0; r < 4; ++r) {
        v[r].x = __expf(v[r].x - mx);
        v[r].y = __expf(v[r].y - mx);
        v[r].z = __expf(v[r].z - mx);
        v[r].w = __expf(v[r].w - mx);
        sum += v[r].x + v[r].y + v[r].z + v[r].w;
    }
    red[tid] = sum;
    __syncthreads();
    for (int off = 128; off > 0; off >>= 1) {
        if (tid < off) red[tid] += red[tid + off];
        __syncthreads();
    }
    const float inv = 1.0f / red[0];
    #pragma unroll
    for (int r = 0; r < 4; ++r) {
        v[r].x *= inv; v[r].y *= inv; v[r].z *= inv; v[r].w *= inv;
        p[tid + 256 * r] = v[r];
    }
}

// ---------------------------------------------------------------------------
extern "C" void kernel_launch(void* const* d_in, const int* in_sizes, int n_in,
                              void* d_out, int out_size) {
    const float* x      = (const float*)d_in[0];
    const float* gn_w   = (const float*)d_in[1];
    const float* gn_b   = (const float*)d_in[2];
    const float* qkv_w  = (const float*)d_in[3];
    const float* qkv_b  = (const float*)d_in[4];
    const float* proj_w = (const float*)d_in[5];
    const float* proj_b = (const float*)d_in[6];
    float* out = (float*)d_out;

    float *h, *qkv, *s, *ao;
    cudaGetSymbolAddress((void**)&h,   g_h);
    cudaGetSymbolAddress((void**)&qkv, g_qkv);
    cudaGetSymbolAddress((void**)&s,   g_s);
    cudaGetSymbolAddress((void**)&ao,  g_ao);

    const size_t CT = (size_t)C_ * T_;
    const size_t TT = (size_t)T_ * T_;

    // 1) GroupNorm
    gn_kernel<<<B_ * G_, 256>>>(x, gn_w, gn_b, h);

    // 2) QKV GEMM: qkv[b,o,t] = qkv_w[o,:] . h[b,:,t] + qkv_b[o]
    gemm_kernel<false, true><<<dim3(T_ / 128, 3 * C_ / 128, B_), 256>>>(
        qkv_w, h, qkv, qkv_b, nullptr,
        3 * C_, T_, C_, C_, T_, T_,
        0, CT, 3 * CT, 0, 1.0f);

    // 3) Scores: S[b,t,s] = (1/sqrt(C)) * q[b,:,t] . k[b,:,s]
    gemm_kernel<true, true><<<dim3(T_ / 128, T_ / 128, B_), 256>>>(
        qkv /*q*/, qkv + CT /*k*/, s, nullptr, nullptr,
        T_, T_, C_, T_, T_, T_,
        3 * CT, 3 * CT, TT, 0, 1.0f / sqrtf((float)C_));

    // 4) Softmax rows
    softmax_kernel<<<B_ * T_, 256>>>(s);

    // 5) AV: ao[b,c,t] = sum_s v[b,c,s] * S[b,t,s]
    gemm_kernel<false, false><<<dim3(T_ / 128, C_ / 128, B_), 256>>>(
        qkv + 2 * CT /*v*/, s, ao, nullptr, nullptr,
        C_, T_, T_, T_, T_, T_,
        3 * CT, TT, CT, 0, 1.0f);

    // 6) Proj + bias + residual
    gemm_kernel<false, true><<<dim3(T_ / 128, C_ / 128, B_), 256>>>(
        proj_w, ao, out, proj_b, x,
        C_, T_, C_, C_, T_, T_,
        0, CT, CT, CT, 1.0f);
}

// round 6
// speedup vs baseline: 2.4137x; 2.4137x over previous
#include <cuda_runtime.h>
#include <cstdint>
#include <math.h>

#define B_  8
#define C_  512
#define T_  4096
#define G_  32
#define CPG 16

// ---------------- scratch (device globals; allocation-free rule) ------------
__device__ float g_hT [(size_t)B_ * T_ * C_];        //  67 MB  groupnorm out  [b][t][c]
__device__ float g_qkT[(size_t)B_ * T_ * 2 * C_];    // 134 MB  q,k transposed [b][t][0:512)=q [512:1024)=k
__device__ float g_v  [(size_t)B_ * C_ * T_];        //  67 MB  v              [b][c][t]
__device__ float g_s  [(size_t)B_ * T_ * T_];        // 536 MB  scores         [b][t][s]
__device__ float g_aoT[(size_t)B_ * T_ * C_];        //  67 MB  attn@V         [b][t][c]
__device__ float g_sc [B_ * C_];
__device__ float g_sh [B_ * C_];

// ---------------- helpers ----------------------------------------------------
__device__ __forceinline__ uint32_t f2tf(float f) {
    uint32_t u; asm("cvt.rna.tf32.f32 %0, %1;" : "=r"(u) : "f"(f)); return u;
}
__device__ __forceinline__ int slot4(int r, int c4) { return r * 32 + (c4 ^ ((r >> 2) & 7)); }

__device__ __forceinline__ void mma8(float* d, const uint32_t* a, const uint32_t* b) {
    asm volatile(
        "mma.sync.aligned.m16n8k8.row.col.f32.tf32.tf32.f32 "
        "{%0,%1,%2,%3}, {%4,%5,%6,%7}, {%8,%9}, {%0,%1,%2,%3};"
        : "+f"(d[0]), "+f"(d[1]), "+f"(d[2]), "+f"(d[3])
        : "r"(a[0]), "r"(a[1]), "r"(a[2]), "r"(a[3]), "r"(b[0]), "r"(b[1]));
}

// ---------------- tf32 mma.sync GEMM ----------------------------------------
// D[m,n] = alpha * sum_k A[m,k] * B[n,k]   (both operands K-contiguous)
// m0 <  split : transposed store  Ct[n][m]  (ld=ldt), +bias[m]
// m0 >= split : normal store      Cn[m0-split+m][n] (ld=ldn), +bias[m], +res
// BM=128, BN=256, BK=16, 256 threads, warp tile 64x64.
// smem (words): A0:0(2560) B0:2560(5120) A1:7680(2560) B1:10240(5120); row stride 20.
__global__ __launch_bounds__(256, 1) void gemm_mma(
    const float* __restrict__ A, const float* __restrict__ Bm,
    float* __restrict__ Cn, float* __restrict__ Ct,
    const float* __restrict__ bias, const float* __restrict__ res,
    int K, int lda, int ldb, int ldn, int ldt,
    size_t sA, size_t sB, size_t sCn, size_t sCt, size_t sR,
    float alpha, int split)
{
    extern __shared__ __align__(16) uint32_t smw[];
    const int tid = threadIdx.x, lane = tid & 31, wid = tid >> 5;
    const int wm = wid & 1, wn = wid >> 1;
    const int m_off = wm * 64, n_off = wn * 64;
    const int g = lane >> 2, tig = lane & 3;
    const int m0 = blockIdx.y * 128, n0 = blockIdx.x * 256, z = blockIdx.z;

    const float* Ag = A  + sA * (size_t)z + (size_t)m0 * lda;
    const float* Bg = Bm + sB * (size_t)z + (size_t)n0 * ldb;

    float acc[4][8][4];
    #pragma unroll
    for (int i = 0; i < 4; ++i)
        #pragma unroll
        for (int j = 0; j < 8; ++j) {
            acc[i][j][0] = 0.f; acc[i][j][1] = 0.f;
            acc[i][j][2] = 0.f; acc[i][j][3] = 0.f;
        }

    float4 ra[2], rb[4];

    auto ldg = [&](int kf) {
        #pragma unroll
        for (int i = 0; i < 2; ++i) {
            int q = tid + 256 * i; int r = q >> 2, c = q & 3;
            ra[i] = *reinterpret_cast<const float4*>(Ag + (size_t)r * lda + kf + 4 * c);
        }
        #pragma unroll
        for (int i = 0; i < 4; ++i) {
            int q = tid + 256 * i; int r = q >> 2, c = q & 3;
            rb[i] = *reinterpret_cast<const float4*>(Bg + (size_t)r * ldb + kf + 4 * c);
        }
    };
    auto sts = [&](int buf) {
        uint32_t* sAp = smw + (buf ? 7680 : 0);
        uint32_t* sBp = smw + (buf ? 10240 : 2560);
        #pragma unroll
        for (int i = 0; i < 2; ++i) {
            int q = tid + 256 * i; int r = q >> 2, c = q & 3;
            uint4 u = make_uint4(f2tf(ra[i].x), f2tf(ra[i].y), f2tf(ra[i].z), f2tf(ra[i].w));
            *reinterpret_cast<uint4*>(sAp + r * 20 + 4 * c) = u;
        }
        #pragma unroll
        for (int i = 0; i < 4; ++i) {
            int q = tid + 256 * i; int r = q >> 2, c = q & 3;
            uint4 u = make_uint4(f2tf(rb[i].x), f2tf(rb[i].y), f2tf(rb[i].z), f2tf(rb[i].w));
            *reinterpret_cast<uint4*>(sBp + r * 20 + 4 * c) = u;
        }
    };
    auto compute = [&](int buf) {
        const uint32_t* sAp = smw + (buf ? 7680 : 0);
        const uint32_t* sBp = smw + (buf ? 10240 : 2560);
        #pragma unroll
        for (int ks = 0; ks < 2; ++ks) {
            const int k0 = ks * 8;
            uint32_t af[4][4], bf[8][2];
            #pragma unroll
            for (int mt = 0; mt < 4; ++mt) {
                const uint32_t* p = sAp + (m_off + mt * 16 + g) * 20 + k0 + tig;
                af[mt][0] = p[0]; af[mt][1] = p[160]; af[mt][2] = p[4]; af[mt][3] = p[164];
            }
            #pragma unroll
            for (int nt = 0; nt < 8; ++nt) {
                const uint32_t* p = sBp + (n_off + nt * 8 + g) * 20 + k0 + tig;
                bf[nt][0] = p[0]; bf[nt][1] = p[4];
            }
            #pragma unroll
            for (int mt = 0; mt < 4; ++mt)
                #pragma unroll
                for (int nt = 0; nt < 8; ++nt)
                    mma8(acc[mt][nt], af[mt], bf[nt]);
        }
    };

    ldg(0); sts(0); __syncthreads();
    const int ntiles = K / 16;
    for (int t = 0; t < ntiles; ++t) {
        if (t + 1 < ntiles) ldg((t + 1) * 16);
        compute(t & 1);
        if (t + 1 < ntiles) sts((t + 1) & 1);
        __syncthreads();
    }

    if (m0 >= split) {
        // ---------------- normal store (direct, v2) ----------------
        float* dst = Cn + sCn * (size_t)z;
        const float* rsrc = res ? res + sR * (size_t)z : nullptr;
        const int mb = m0 - split;
        #pragma unroll
        for (int mt = 0; mt < 4; ++mt) {
            int rml = m_off + mt * 16 + g;
            float b0 = bias ? bias[m0 + rml]     : 0.f;
            float b1 = bias ? bias[m0 + rml + 8] : 0.f;
            #pragma unroll
            for (int nt = 0; nt < 8; ++nt) {
                int col = n0 + n_off + nt * 8 + 2 * tig;
                size_t i0 = (size_t)(mb + rml)     * ldn + col;
                size_t i1 = (size_t)(mb + rml + 8) * ldn + col;
                float2 v0, v1;
                v0.x = alpha * acc[mt][nt][0] + b0;
                v0.y = alpha * acc[mt][nt][1] + b0;
                v1.x = alpha * acc[mt][nt][2] + b1;
                v1.y = alpha * acc[mt][nt][3] + b1;
                if (rsrc) {
                    float2 r0 = *reinterpret_cast<const float2*>(rsrc + i0);
                    float2 r1 = *reinterpret_cast<const float2*>(rsrc + i1);
                    v0.x += r0.x; v0.y += r0.y; v1.x += r1.x; v1.y += r1.y;
                }
                *reinterpret_cast<float2*>(dst + i0) = v0;
                *reinterpret_cast<float2*>(dst + i1) = v1;
            }
        }
    } else {
        // ---------------- transposed store via smem staging ----------------
        float* smf = reinterpret_cast<float*>(smw);
        float* dst = Ct + sCt * (size_t)z;
        #pragma unroll
        for (int h = 0; h < 2; ++h) {
            __syncthreads();
            if ((wn >> 1) == h) {
                #pragma unroll
                for (int mt = 0; mt < 4; ++mt) {
                    int rml = m_off + mt * 16 + g;
                    float b0 = bias ? bias[m0 + rml]     : 0.f;
                    float b1 = bias ? bias[m0 + rml + 8] : 0.f;
                    #pragma unroll
                    for (int nt = 0; nt < 8; ++nt) {
                        int nl = (wn & 1) * 64 + nt * 8 + 2 * tig;
                        float2 v0, v1;
                        v0.x = alpha * acc[mt][nt][0] + b0;
                        v0.y = alpha * acc[mt][nt][1] + b0;
                        v1.x = alpha * acc[mt][nt][2] + b1;
                        v1.y = alpha * acc[mt][nt][3] + b1;
                        *reinterpret_cast<float2*>(smf + 4 * slot4(rml,     nl >> 2) + (nl & 3)) = v0;
                        *reinterpret_cast<float2*>(smf + 4 * slot4(rml + 8, nl >> 2) + (nl & 3)) = v1;
                    }
                }
            }
            __syncthreads();
            #pragma unroll 2
            for (int i = 0; i < 16; ++i) {
                int oq = tid + 256 * i;
                int n = oq >> 5, m4 = oq & 31;
                float4 v;
                v.x = smf[4 * slot4(4 * m4 + 0, n >> 2) + (n & 3)];
                v.y = smf[4 * slot4(4 * m4 + 1, n >> 2) + (n & 3)];
                v.z = smf[4 * slot4(4 * m4 + 2, n >> 2) + (n & 3)];
                v.w = smf[4 * slot4(4 * m4 + 3, n >> 2) + (n & 3)];
                *reinterpret_cast<float4*>(
                    dst + (size_t)(n0 + 128 * h + n) * ldt + m0 + 4 * m4) = v;
            }
        }
    }
}

// ---------------- GroupNorm pass 1: per-(b,g) stats -> per-channel sc/sh ----
__global__ __launch_bounds__(256) void gn_stats(const float* __restrict__ x,
                                                const float* __restrict__ w,
                                                const float* __restrict__ bb,
                                                float* __restrict__ sc,
                                                float* __restrict__ sh) {
    const int bg = blockIdx.x;
    const int bi = bg >> 5;
    const int g  = bg & 31;
    const size_t base = ((size_t)bi * C_ + (size_t)g * CPG) * T_;
    const float4* xp4 = reinterpret_cast<const float4*>(x + base);
    const int n4 = CPG * T_ / 4;
    float s = 0.f, s2 = 0.f;
    for (int i = threadIdx.x; i < n4; i += 256) {
        float4 v = xp4[i];
        s  += v.x + v.y + v.z + v.w;
        s2 += v.x * v.x + v.y * v.y + v.z * v.z + v.w * v.w;
    }
    __shared__ float rs[256], rq[256];
    rs[threadIdx.x] = s; rq[threadIdx.x] = s2;
    __syncthreads();
    for (int off = 128; off > 0; off >>= 1) {
        if (threadIdx.x < off) {
            rs[threadIdx.x] += rs[threadIdx.x + off];
            rq[threadIdx.x] += rq[threadIdx.x + off];
        }
        __syncthreads();
    }
    const float inv_n = 1.0f / (float)(CPG * T_);
    const float mean  = rs[0] * inv_n;
    const float var   = rq[0] * inv_n - mean * mean;
    const float rstd  = rsqrtf(var + 1e-5f);
    if (threadIdx.x < CPG) {
        int c = g * CPG + threadIdx.x;
        float scv = w[c] * rstd;
        sc[bi * C_ + c] = scv;
        sh[bi * C_ + c] = bb[c] - mean * scv;
    }
}

// ---------------- GroupNorm pass 2: normalize + transpose -> hT[b][t][c] ----
__global__ __launch_bounds__(256) void gn_tr(const float* __restrict__ x,
                                             const float* __restrict__ sc,
                                             const float* __restrict__ sh,
                                             float* __restrict__ hT) {
    extern __shared__ __align__(1024) char smem[];
    float* smf = reinterpret_cast<float*>(smem);
    const int t0 = blockIdx.x * 128, c0 = blockIdx.y * 128, z = blockIdx.z;
    const int tid = threadIdx.x;
    #pragma unroll 4
    for (int i = 0; i < 16; ++i) {
        int q = tid + 256 * i;
        int row = q >> 5, t4 = q & 31;           // row = local c
        int c = c0 + row;
        float scv = sc[z * C_ + c], shv = sh[z * C_ + c];
        float4 v = *reinterpret_cast<const float4*>(
            x + ((size_t)z * C_ + c) * T_ + t0 + 4 * t4);
        v.x = v.x * scv + shv; v.y = v.y * scv + shv;
        v.z = v.z * scv + shv; v.w = v.w * scv + shv;
        *reinterpret_cast<float4*>(smf + 4 * slot4(row, t4)) = v;
    }
    __syncthreads();
    #pragma unroll 4
    for (int i = 0; i < 16; ++i) {
        int oq = tid + 256 * i;
        int t = oq >> 5, c4 = oq & 31;
        float4 v;
        v.x = smf[4 * slot4(4 * c4 + 0, t >> 2) + (t & 3)];
        v.y = smf[4 * slot4(4 * c4 + 1, t >> 2) + (t & 3)];
        v.z = smf[4 * slot4(4 * c4 + 2, t >> 2) + (t & 3)];
        v.w = smf[4 * slot4(4 * c4 + 3, t >> 2) + (t & 3)];
        *reinterpret_cast<float4*>(hT + ((size_t)z * T_ + t0 + t) * C_ + c0 + 4 * c4) = v;
    }
}

// ---------------- Row softmax over 4096 cols --------------------------------
__global__ __launch_bounds__(256) void softmax_kernel(float* __restrict__ s) {
    float4* p = reinterpret_cast<float4*>(s + (size_t)blockIdx.x * T_);
    const int tid = threadIdx.x;
    float4 v[4];
    float mx = -1e30f;
    #pragma unroll
    for (int r = 0; r < 4; ++r) {
        v[r] = p[tid + 256 * r];
        mx = fmaxf(mx, fmaxf(fmaxf(v[r].x, v[r].y), fmaxf(v[r].z, v[r].w)));
    }
    __shared__ float red[256];
    red[tid] = mx;
    __syncthreads();
    for (int off = 128; off > 0; off >>= 1) {
        if (tid < off) red[tid] = fmaxf(red[tid], red[tid + off]);
        __syncthreads();
    }
    mx = red[0];
    __syncthreads();
    float sum = 0.f;
    #pragma unroll
    for (int r = 0; r < 4; ++r) {
        v[r].x = __expf(v[r].x - mx); v[r].y = __expf(v[r].y - mx);
        v[r].z = __expf(v[r].z - mx); v[r].w = __expf(v[r].w - mx);
        sum += v[r].x + v[r].y + v[r].z + v[r].w;
    }
    red[tid] = sum;
    __syncthreads();
    for (int off = 128; off > 0; off >>= 1) {
        if (tid < off) red[tid] += red[tid + off];
        __syncthreads();
    }
    const float inv = 1.0f / red[0];
    #pragma unroll
    for (int r = 0; r < 4; ++r) {
        v[r].x *= inv; v[r].y *= inv; v[r].z *= inv; v[r].w *= inv;
        p[tid + 256 * r] = v[r];
    }
}

// ---------------------------------------------------------------------------
extern "C" void kernel_launch(void* const* d_in, const int* in_sizes, int n_in,
                              void* d_out, int out_size) {
    const float* x      = (const float*)d_in[0];
    const float* gn_w   = (const float*)d_in[1];
    const float* gn_b   = (const float*)d_in[2];
    const float* qkv_w  = (const float*)d_in[3];
    const float* qkv_b  = (const float*)d_in[4];
    const float* proj_w = (const float*)d_in[5];
    const float* proj_b = (const float*)d_in[6];
    float* out = (float*)d_out;

    float *hT, *qkT, *v, *s, *aoT, *sc, *sh;
    cudaGetSymbolAddress((void**)&hT,  g_hT);
    cudaGetSymbolAddress((void**)&qkT, g_qkT);
    cudaGetSymbolAddress((void**)&v,   g_v);
    cudaGetSymbolAddress((void**)&s,   g_s);
    cudaGetSymbolAddress((void**)&aoT, g_aoT);
    cudaGetSymbolAddress((void**)&sc,  g_sc);
    cudaGetSymbolAddress((void**)&sh,  g_sh);

    cudaFuncSetAttribute(gemm_mma, cudaFuncAttributeMaxDynamicSharedMemorySize, 65536);
    cudaFuncSetAttribute(gn_tr,    cudaFuncAttributeMaxDynamicSharedMemorySize, 65536);

    const size_t CT = (size_t)C_ * T_;
    const size_t TT = (size_t)T_ * T_;
    const size_t TC = (size_t)T_ * C_;
    const size_t T2C = (size_t)T_ * 2 * C_;

    // 1) GroupNorm stats + normalize/transpose -> hT[b][t][c]
    gn_stats<<<B_ * G_, 256>>>(x, gn_w, gn_b, sc, sh);
    gn_tr<<<dim3(T_ / 128, C_ / 128, B_), 256, 65536>>>(x, sc, sh, hT);

    // 2) QKV: D[o,t] = W[o,:] . hT[t,:] + b ; o<1024 -> qkT[t][o] ; o>=1024 -> v[o-1024][t]
    gemm_mma<<<dim3(T_ / 256, 3 * C_ / 128, B_), 256, 65536>>>(
        qkv_w, hT, v, qkT, qkv_b, nullptr,
        C_, C_, C_, T_, 2 * C_,
        0, TC, CT, T2C, 0,
        1.0f, 2 * C_);

    // 3) Scores: S[t,n] = alpha * q[t,:] . k[n,:]   (normal direct store)
    gemm_mma<<<dim3(T_ / 256, T_ / 128, B_), 256, 65536>>>(
        qkT, qkT + C_, s, nullptr, nullptr, nullptr,
        C_, 2 * C_, 2 * C_, T_, 0,
        T2C, T2C, TT, 0, 0,
        0.04419417382415922f /* 1/sqrt(512) */, 0);

    // 4) Softmax
    softmax_kernel<<<B_ * T_, 256>>>(s);

    // 5) AV: D[c,t] = v[c,:] . S[t,:]  -> transposed -> aoT[t][c]
    gemm_mma<<<dim3(T_ / 256, C_ / 128, B_), 256, 65536>>>(
        v, s, nullptr, aoT, nullptr, nullptr,
        T_, T_, T_, 0, C_,
        CT, TT, 0, TC, 0,
        1.0f, C_);

    // 6) Proj + bias + residual: out[c,t] = Pw[c,:] . aoT[t,:] + pb + x
    gemm_mma<<<dim3(T_ / 256, C_ / 128, B_), 256, 65536>>>(
        proj_w, aoT, out, nullptr, proj_b, x,
        C_, C_, C_, T_, 0,
        0, TC, CT, 0, CT,
        1.0f, 0);
}

// round 7
// speedup vs baseline: 5.2328x; 2.1679x over previous
#include <cuda_runtime.h>
#include <cuda_bf16.h>
#include <cstdint>
#include <math.h>

#define B_  8
#define C_  512
#define T_  4096
#define G_  32
#define CPG 16

typedef __nv_bfloat16 bf16;

// ---------------- scratch (device globals; allocation-free rule) ------------
__device__ bf16  g_hT [(size_t)B_ * T_ * C_];        // groupnorm out  [b][t][c]   33 MB
__device__ bf16  g_qkT[(size_t)B_ * T_ * 2 * C_];    // q,k            [b][t][0:1024) 67 MB
__device__ bf16  g_v  [(size_t)B_ * C_ * T_];        // v              [b][c][t]   33 MB
__device__ float g_s  [(size_t)B_ * T_ * T_];        // scores f32     [b][t][s]  536 MB
__device__ bf16  g_p  [(size_t)B_ * T_ * T_];        // attn bf16      [b][t][s]  268 MB
__device__ bf16  g_aoT[(size_t)B_ * T_ * C_];        // attn@V         [b][t][c]   33 MB
__device__ bf16  g_wq [3 * C_ * C_];                 // qkv_w bf16
__device__ bf16  g_wp [C_ * C_];                     // proj_w bf16
__device__ float g_sc [B_ * C_];
__device__ float g_sh [B_ * C_];

// ---------------- helpers ----------------------------------------------------
__device__ __forceinline__ uint32_t smem_u32(const void* p) {
    uint32_t a;
    asm("{ .reg .u64 t; cvta.to.shared.u64 t, %1; cvt.u32.u64 %0, t; }" : "=r"(a) : "l"(p));
    return a;
}
__device__ __forceinline__ void mma16(float* d, const uint32_t* a, const uint32_t* b) {
    asm volatile(
        "mma.sync.aligned.m16n8k16.row.col.f32.bf16.bf16.f32 "
        "{%0,%1,%2,%3}, {%4,%5,%6,%7}, {%8,%9}, {%0,%1,%2,%3};"
        : "+f"(d[0]), "+f"(d[1]), "+f"(d[2]), "+f"(d[3])
        : "r"(a[0]), "r"(a[1]), "r"(a[2]), "r"(a[3]), "r"(b[0]), "r"(b[1]));
}
__device__ __forceinline__ void ldsm4(uint32_t* r, uint32_t addr) {
    asm volatile("ldmatrix.sync.aligned.m8n8.x4.shared.b16 {%0,%1,%2,%3}, [%4];"
        : "=r"(r[0]), "=r"(r[1]), "=r"(r[2]), "=r"(r[3]) : "r"(addr));
}
__device__ __forceinline__ void cpa16(uint32_t dst, const void* src) {
    asm volatile("cp.async.cg.shared.global [%0], [%1], 16;" :: "r"(dst), "l"(src));
}
#define CPA_COMMIT() asm volatile("cp.async.commit_group;" ::: "memory")
__device__ __forceinline__ int slot4(int r, int c4) { return r * 32 + (c4 ^ ((r >> 2) & 7)); }

// ---------------- bf16 mma GEMM: D[m,n] = alpha*sum_k A[m,k]*B[n,k] ----------
// BM=BN=128, BK=32, 256 threads, warp tile 64x32 (2x4 warps), cp.async 3-stage.
// OUTF32: f32 store (+res); else bf16 store. BIASCOL: bias indexed by col, else row.
// smem: 3 stages x (A 2560w + B 2560w), rows padded to 20 words (80B).
template<bool OUTF32, bool BIASCOL>
__global__ __launch_bounds__(256, 2) void gemm_bf16(
    const bf16* __restrict__ A, const bf16* __restrict__ Bm,
    void* __restrict__ D, const float* __restrict__ bias, const float* __restrict__ res,
    int K, int lda, int ldb, int ldd,
    size_t sA, size_t sB, size_t sD, size_t sR, float alpha)
{
    extern __shared__ __align__(16) uint32_t smw[];
    const uint32_t sb = smem_u32(smw);
    const int tid = threadIdx.x, lane = tid & 31, wid = tid >> 5;
    const int m_off = (wid & 1) * 64, n_off = (wid >> 1) * 32;
    const int g = lane >> 2, tig = lane & 3;
    const int row16 = lane & 15, half = lane >> 4;
    const int m0 = blockIdx.y * 128, n0 = blockIdx.x * 128, z = blockIdx.z;

    const bf16* Ag = A  + sA * (size_t)z + (size_t)m0 * lda;
    const bf16* Bg = Bm + sB * (size_t)z + (size_t)n0 * ldb;

    float acc[4][4][4];
    #pragma unroll
    for (int i = 0; i < 4; ++i)
        #pragma unroll
        for (int j = 0; j < 4; ++j)
            #pragma unroll
            for (int e = 0; e < 4; ++e) acc[i][j][e] = 0.f;

    const int r_ = tid >> 2, c_ = tid & 3;          // cp.async coords
    auto issue = [&](int t, int s) {
        uint32_t dA = sb + (s * 5120 + r_ * 20 + c_ * 4) * 4;
        uint32_t dB = dA + 2560 * 4;
        const bf16* as = Ag + t * 32;
        const bf16* bs = Bg + t * 32;
        cpa16(dA,            as + (size_t)r_ * lda + c_ * 8);
        cpa16(dA + 64 * 80,  as + (size_t)(r_ + 64) * lda + c_ * 8);
        cpa16(dB,            bs + (size_t)r_ * ldb + c_ * 8);
        cpa16(dB + 64 * 80,  bs + (size_t)(r_ + 64) * ldb + c_ * 8);
        CPA_COMMIT();
    };
    auto compute = [&](int s) {
        const uint32_t base  = sb + s * 5120 * 4;
        const uint32_t aBase = base + (m_off + row16) * 80 + half * 16;
        const uint32_t bBase = base + 2560 * 4 + (n_off + row16) * 80 + half * 16;
        #pragma unroll
        for (int ks = 0; ks < 2; ++ks) {
            uint32_t af[4][4], bq[2][4];
            #pragma unroll
            for (int mt = 0; mt < 4; ++mt) ldsm4(af[mt], aBase + mt * 1280 + ks * 32);
            #pragma unroll
            for (int p = 0; p < 2; ++p)    ldsm4(bq[p], bBase + p * 1280 + ks * 32);
            #pragma unroll
            for (int mt = 0; mt < 4; ++mt)
                #pragma unroll
                for (int nt = 0; nt < 4; ++nt) {
                    uint32_t bfr[2] = { bq[nt >> 1][nt & 1], bq[nt >> 1][(nt & 1) + 2] };
                    mma16(acc[mt][nt], af[mt], bfr);
                }
        }
    };

    const int ntl = K / 32;
    issue(0, 0);
    if (ntl > 1) issue(1, 1);
    for (int t = 0; t < ntl; ++t) {
        if (t + 2 < ntl) {
            issue(t + 2, (t + 2) % 3);
            asm volatile("cp.async.wait_group 2;" ::: "memory");
        } else if (t + 1 < ntl) {
            asm volatile("cp.async.wait_group 1;" ::: "memory");
        } else {
            asm volatile("cp.async.wait_group 0;" ::: "memory");
        }
        __syncthreads();
        compute(t % 3);
        __syncthreads();
    }

    // ---------------- epilogue: direct normal store ----------------
    #pragma unroll
    for (int mt = 0; mt < 4; ++mt) {
        const int rml = m_off + mt * 16 + g;
        float rb0 = 0.f, rb1 = 0.f;
        if (!BIASCOL && bias) { rb0 = bias[m0 + rml]; rb1 = bias[m0 + rml + 8]; }
        #pragma unroll
        for (int nt = 0; nt < 4; ++nt) {
            const int col = n0 + n_off + nt * 8 + 2 * tig;
            float2 cb = make_float2(0.f, 0.f);
            if (BIASCOL && bias) cb = *reinterpret_cast<const float2*>(bias + col);
            float v0x = alpha * acc[mt][nt][0], v0y = alpha * acc[mt][nt][1];
            float v1x = alpha * acc[mt][nt][2], v1y = alpha * acc[mt][nt][3];
            if (BIASCOL) { v0x += cb.x; v0y += cb.y; v1x += cb.x; v1y += cb.y; }
            else         { v0x += rb0;  v0y += rb0;  v1x += rb1;  v1y += rb1;  }
            size_t i0 = (size_t)(m0 + rml)     * ldd + col;
            size_t i1 = (size_t)(m0 + rml + 8) * ldd + col;
            if (OUTF32) {
                float* dst = (float*)D + sD * (size_t)z;
                if (res) {
                    const float* rp = res + sR * (size_t)z;
                    float2 r0 = *reinterpret_cast<const float2*>(rp + i0);
                    float2 r1 = *reinterpret_cast<const float2*>(rp + i1);
                    v0x += r0.x; v0y += r0.y; v1x += r1.x; v1y += r1.y;
                }
                *reinterpret_cast<float2*>(dst + i0) = make_float2(v0x, v0y);
                *reinterpret_cast<float2*>(dst + i1) = make_float2(v1x, v1y);
            } else {
                bf16* dst = (bf16*)D + sD * (size_t)z;
                *reinterpret_cast<__nv_bfloat162*>(dst + i0) =
                    __float22bfloat162_rn(make_float2(v0x, v0y));
                *reinterpret_cast<__nv_bfloat162*>(dst + i1) =
                    __float22bfloat162_rn(make_float2(v1x, v1y));
            }
        }
    }
}

// ---------------- fp32 -> bf16 weight convert -------------------------------
__global__ void cvt_kernel(const float* __restrict__ src, bf16* __restrict__ dst, int n4) {
    int i = blockIdx.x * 256 + threadIdx.x;
    if (i < n4) {
        float4 v = reinterpret_cast<const float4*>(src)[i];
        __nv_bfloat162 a = __float22bfloat162_rn(make_float2(v.x, v.y));
        __nv_bfloat162 b = __float22bfloat162_rn(make_float2(v.z, v.w));
        reinterpret_cast<uint2*>(dst)[i] = make_uint2(
            *reinterpret_cast<uint32_t*>(&a), *reinterpret_cast<uint32_t*>(&b));
    }
}

// ---------------- GroupNorm pass 1 ------------------------------------------
__global__ __launch_bounds__(256) void gn_stats(const float* __restrict__ x,
                                                const float* __restrict__ w,
                                                const float* __restrict__ bb,
                                                float* __restrict__ sc,
                                                float* __restrict__ sh) {
    const int bg = blockIdx.x;
    const int bi = bg >> 5;
    const int g  = bg & 31;
    const size_t base = ((size_t)bi * C_ + (size_t)g * CPG) * T_;
    const float4* xp4 = reinterpret_cast<const float4*>(x + base);
    const int n4 = CPG * T_ / 4;
    float s = 0.f, s2 = 0.f;
    for (int i = threadIdx.x; i < n4; i += 256) {
        float4 v = xp4[i];
        s  += v.x + v.y + v.z + v.w;
        s2 += v.x * v.x + v.y * v.y + v.z * v.z + v.w * v.w;
    }
    __shared__ float rs[256], rq[256];
    rs[threadIdx.x] = s; rq[threadIdx.x] = s2;
    __syncthreads();
    for (int off = 128; off > 0; off >>= 1) {
        if (threadIdx.x < off) {
            rs[threadIdx.x] += rs[threadIdx.x + off];
            rq[threadIdx.x] += rq[threadIdx.x + off];
        }
        __syncthreads();
    }
    const float inv_n = 1.0f / (float)(CPG * T_);
    const float mean  = rs[0] * inv_n;
    const float var   = rq[0] * inv_n - mean * mean;
    const float rstd  = rsqrtf(var + 1e-5f);
    if (threadIdx.x < CPG) {
        int c = g * CPG + threadIdx.x;
        float scv = w[c] * rstd;
        sc[bi * C_ + c] = scv;
        sh[bi * C_ + c] = bb[c] - mean * scv;
    }
}

// ---------------- GroupNorm pass 2: normalize + transpose -> bf16 hT --------
__global__ __launch_bounds__(256) void gn_tr(const float* __restrict__ x,
                                             const float* __restrict__ sc,
                                             const float* __restrict__ sh,
                                             bf16* __restrict__ hT) {
    extern __shared__ __align__(1024) char smem[];
    float* smf = reinterpret_cast<float*>(smem);
    const int t0 = blockIdx.x * 128, c0 = blockIdx.y * 128, z = blockIdx.z;
    const int tid = threadIdx.x;
    #pragma unroll 4
    for (int i = 0; i < 16; ++i) {
        int q = tid + 256 * i;
        int row = q >> 5, t4 = q & 31;           // row = local c
        int c = c0 + row;
        float scv = sc[z * C_ + c], shv = sh[z * C_ + c];
        float4 v = *reinterpret_cast<const float4*>(
            x + ((size_t)z * C_ + c) * T_ + t0 + 4 * t4);
        v.x = v.x * scv + shv; v.y = v.y * scv + shv;
        v.z = v.z * scv + shv; v.w = v.w * scv + shv;
        *reinterpret_cast<float4*>(smf + 4 * slot4(row, t4)) = v;
    }
    __syncthreads();
    #pragma unroll 4
    for (int i = 0; i < 16; ++i) {
        int oq = tid + 256 * i;
        int t = oq >> 5, c4 = oq & 31;
        float4 v;
        v.x = smf[4 * slot4(4 * c4 + 0, t >> 2) + (t & 3)];
        v.y = smf[4 * slot4(4 * c4 + 1, t >> 2) + (t & 3)];
        v.z = smf[4 * slot4(4 * c4 + 2, t >> 2) + (t & 3)];
        v.w = smf[4 * slot4(4 * c4 + 3, t >> 2) + (t & 3)];
        __nv_bfloat162 a = __float22bfloat162_rn(make_float2(v.x, v.y));
        __nv_bfloat162 b = __float22bfloat162_rn(make_float2(v.z, v.w));
        *reinterpret_cast<uint2*>(hT + ((size_t)z * T_ + t0 + t) * C_ + c0 + 4 * c4) =
            make_uint2(*reinterpret_cast<uint32_t*>(&a), *reinterpret_cast<uint32_t*>(&b));
    }
}

// ---------------- Row softmax: f32 in -> bf16 out ---------------------------
__global__ __launch_bounds__(256) void softmax_kernel(const float* __restrict__ s,
                                                      bf16* __restrict__ p) {
    const float4* ip = reinterpret_cast<const float4*>(s + (size_t)blockIdx.x * T_);
    uint2* op = reinterpret_cast<uint2*>(p + (size_t)blockIdx.x * T_);
    const int tid = threadIdx.x;
    float4 v[4];
    float mx = -1e30f;
    #pragma unroll
    for (int r = 0; r < 4; ++r) {
        v[r] = ip[tid + 256 * r];
        mx = fmaxf(mx, fmaxf(fmaxf(v[r].x, v[r].y), fmaxf(v[r].z, v[r].w)));
    }
    __shared__ float red[256];
    red[tid] = mx;
    __syncthreads();
    for (int off = 128; off > 0; off >>= 1) {
        if (tid < off) red[tid] = fmaxf(red[tid], red[tid + off]);
        __syncthreads();
    }
    mx = red[0];
    __syncthreads();
    float sum = 0.f;
    #pragma unroll
    for (int r = 0; r < 4; ++r) {
        v[r].x = __expf(v[r].x - mx); v[r].y = __expf(v[r].y - mx);
        v[r].z = __expf(v[r].z - mx); v[r].w = __expf(v[r].w - mx);
        sum += v[r].x + v[r].y + v[r].z + v[r].w;
    }
    red[tid] = sum;
    __syncthreads();
    for (int off = 128; off > 0; off >>= 1) {
        if (tid < off) red[tid] += red[tid + off];
        __syncthreads();
    }
    const float inv = 1.0f / red[0];
    #pragma unroll
    for (int r = 0; r < 4; ++r) {
        __nv_bfloat162 a = __float22bfloat162_rn(make_float2(v[r].x * inv, v[r].y * inv));
        __nv_bfloat162 b = __float22bfloat162_rn(make_float2(v[r].z * inv, v[r].w * inv));
        op[tid + 256 * r] = make_uint2(
            *reinterpret_cast<uint32_t*>(&a), *reinterpret_cast<uint32_t*>(&b));
    }
}

// ---------------------------------------------------------------------------
extern "C" void kernel_launch(void* const* d_in, const int* in_sizes, int n_in,
                              void* d_out, int out_size) {
    const float* x      = (const float*)d_in[0];
    const float* gn_w   = (const float*)d_in[1];
    const float* gn_b   = (const float*)d_in[2];
    const float* qkv_w  = (const float*)d_in[3];
    const float* qkv_b  = (const float*)d_in[4];
    const float* proj_w = (const float*)d_in[5];
    const float* proj_b = (const float*)d_in[6];
    float* out = (float*)d_out;

    bf16 *hT, *qkT, *v, *p, *aoT, *wq, *wp;
    float *s, *sc, *sh;
    cudaGetSymbolAddress((void**)&hT,  g_hT);
    cudaGetSymbolAddress((void**)&qkT, g_qkT);
    cudaGetSymbolAddress((void**)&v,   g_v);
    cudaGetSymbolAddress((void**)&s,   g_s);
    cudaGetSymbolAddress((void**)&p,   g_p);
    cudaGetSymbolAddress((void**)&aoT, g_aoT);
    cudaGetSymbolAddress((void**)&wq,  g_wq);
    cudaGetSymbolAddress((void**)&wp,  g_wp);
    cudaGetSymbolAddress((void**)&sc,  g_sc);
    cudaGetSymbolAddress((void**)&sh,  g_sh);

    const int GSM = 61440;
    cudaFuncSetAttribute(gemm_bf16<false, true>,  cudaFuncAttributeMaxDynamicSharedMemorySize, GSM);
    cudaFuncSetAttribute(gemm_bf16<false, false>, cudaFuncAttributeMaxDynamicSharedMemorySize, GSM);
    cudaFuncSetAttribute(gemm_bf16<true,  false>, cudaFuncAttributeMaxDynamicSharedMemorySize, GSM);
    cudaFuncSetAttribute(gn_tr, cudaFuncAttributeMaxDynamicSharedMemorySize, 65536);

    const size_t CT  = (size_t)C_ * T_;
    const size_t TT  = (size_t)T_ * T_;
    const size_t TC  = (size_t)T_ * C_;
    const size_t T2C = (size_t)T_ * 2 * C_;

    // 0) weight conversion fp32 -> bf16
    cvt_kernel<<<(3 * C_ * C_ / 4 + 255) / 256, 256>>>(qkv_w, wq, 3 * C_ * C_ / 4);
    cvt_kernel<<<(C_ * C_ / 4 + 255) / 256, 256>>>(proj_w, wp, C_ * C_ / 4);

    // 1) GroupNorm
    gn_stats<<<B_ * G_, 256>>>(x, gn_w, gn_b, sc, sh);
    gn_tr<<<dim3(T_ / 128, C_ / 128, B_), 256, 65536>>>(x, sc, sh, hT);

    // 2a) QK: D[t,o] = hT[t,:].W[o,:] + b[o] (col bias) -> qkT[t][o], o<1024
    gemm_bf16<false, true><<<dim3(1024 / 128, T_ / 128, B_), 256, GSM>>>(
        hT, wq, qkT, qkv_b, nullptr,
        C_, C_, C_, 2 * C_,
        TC, 0, T2C, 0, 1.0f);

    // 2b) V: D[c,t] = Wv[c,:].hT[t,:] + b (row bias) -> v[c][t]
    gemm_bf16<false, false><<<dim3(T_ / 128, C_ / 128, B_), 256, GSM>>>(
        wq + 2 * C_ * C_, hT, v, qkv_b + 2 * C_, nullptr,
        C_, C_, C_, T_,
        0, TC, CT, 0, 1.0f);

    // 3) Scores: S[t,n] = alpha * q[t,:].k[n,:]  (f32)
    gemm_bf16<true, false><<<dim3(T_ / 128, T_ / 128, B_), 256, GSM>>>(
        qkT, qkT + C_, s, nullptr, nullptr,
        C_, 2 * C_, 2 * C_, T_,
        T2C, T2C, TT, 0, 0.04419417382415922f);

    // 4) Softmax -> bf16 attn
    softmax_kernel<<<B_ * T_, 256>>>(s, p);

    // 5) AV: D[t,c] = attn[t,:].v[c,:] -> aoT[t][c]
    gemm_bf16<false, false><<<dim3(C_ / 128, T_ / 128, B_), 256, GSM>>>(
        p, v, aoT, nullptr, nullptr,
        T_, T_, T_, C_,
        TT, CT, TC, 0, 1.0f);

    // 6) Proj: out[c,t] = Wp[c,:].aoT[t,:] + pb[c] + x  (f32)
    gemm_bf16<true, false><<<dim3(T_ / 128, C_ / 128, B_), 256, GSM>>>(
        wp, aoT, out, proj_b, x,
        C_, C_, C_, T_,
        0, TC, CT, CT, 1.0f);
}

// round 9
// speedup vs baseline: 5.5139x; 1.0537x over previous
#include <cuda_runtime.h>
#include <cuda_fp16.h>
#include <cstdint>
#include <math.h>

#define B_  8
#define C_  512
#define T_  4096
#define G_  32
#define CPG 16

typedef __half half_t;

// ---------------- scratch (device globals; allocation-free rule) ------------
__device__ half_t g_hT [(size_t)B_ * T_ * C_];        // groupnorm out  [b][t][c]
__device__ half_t g_qkT[(size_t)B_ * T_ * 2 * C_];    // q,k            [b][t][0:1024)
__device__ half_t g_v  [(size_t)B_ * C_ * T_];        // v              [b][c][t]
__device__ half_t g_s  [(size_t)B_ * T_ * T_];        // scores/attn fp16 [b][t][s] 268 MB
__device__ half_t g_aoT[(size_t)B_ * T_ * C_];        // attn@V         [b][t][c]
__device__ half_t g_wq [3 * C_ * C_];
__device__ half_t g_wp [C_ * C_];
__device__ float  g_sc [B_ * C_];
__device__ float  g_sh [B_ * C_];

// ---------------- helpers ----------------------------------------------------
__device__ __forceinline__ uint32_t smem_u32(const void* p) {
    uint32_t a;
    asm("{ .reg .u64 t; cvta.to.shared.u64 t, %1; cvt.u32.u64 %0, t; }" : "=r"(a) : "l"(p));
    return a;
}
__device__ __forceinline__ void mma16(float* d, const uint32_t* a, const uint32_t* b) {
    asm volatile(
        "mma.sync.aligned.m16n8k16.row.col.f32.f16.f16.f32 "
        "{%0,%1,%2,%3}, {%4,%5,%6,%7}, {%8,%9}, {%0,%1,%2,%3};"
        : "+f"(d[0]), "+f"(d[1]), "+f"(d[2]), "+f"(d[3])
        : "r"(a[0]), "r"(a[1]), "r"(a[2]), "r"(a[3]), "r"(b[0]), "r"(b[1]));
}
__device__ __forceinline__ void ldsm4(uint32_t* r, uint32_t addr) {
    asm volatile("ldmatrix.sync.aligned.m8n8.x4.shared.b16 {%0,%1,%2,%3}, [%4];"
        : "=r"(r[0]), "=r"(r[1]), "=r"(r[2]), "=r"(r[3]) : "r"(addr));
}
__device__ __forceinline__ void cpa16(uint32_t dst, const void* src) {
    asm volatile("cp.async.cg.shared.global [%0], [%1], 16;" :: "r"(dst), "l"(src));
}
#define CPA_COMMIT() asm volatile("cp.async.commit_group;" ::: "memory")
__device__ __forceinline__ int slot4(int r, int c4) { return r * 32 + (c4 ^ ((r >> 2) & 7)); }

// ---------------- fp16 mma GEMM: D[m,n] = alpha*sum_k A[m,k]*B[n,k] ----------
// BM=BN=128, BK=32, 256 threads, warp tile 64x32, cp.async 4-stage, 1 sync/tile.
// OUTF32: f32 store (+res); else fp16 store. BIASCOL: bias by col, else by row.
// smem: 4 stages x (A 2560w + B 2560w), rows padded to 20 words (80B).
template<bool OUTF32, bool BIASCOL>
__global__ __launch_bounds__(256, 2) void gemm_f16(
    const half_t* __restrict__ A, const half_t* __restrict__ Bm,
    void* __restrict__ D, const float* __restrict__ bias, const float* __restrict__ res,
    int K, int lda, int ldb, int ldd,
    size_t sA, size_t sB, size_t sD, size_t sR, float alpha)
{
    extern __shared__ __align__(16) uint32_t smw[];
    const uint32_t sb = smem_u32(smw);
    const int tid = threadIdx.x, lane = tid & 31, wid = tid >> 5;
    const int m_off = (wid & 1) * 64, n_off = (wid >> 1) * 32;
    const int g = lane >> 2, tig = lane & 3;
    const int row16 = lane & 15, half_ = lane >> 4;
    const int m0 = blockIdx.y * 128, n0 = blockIdx.x * 128, z = blockIdx.z;

    const half_t* Ag = A  + sA * (size_t)z + (size_t)m0 * lda;
    const half_t* Bg = Bm + sB * (size_t)z + (size_t)n0 * ldb;

    float acc[4][4][4];
    #pragma unroll
    for (int i = 0; i < 4; ++i)
        #pragma unroll
        for (int j = 0; j < 4; ++j)
            #pragma unroll
            for (int e = 0; e < 4; ++e) acc[i][j][e] = 0.f;

    const int r_ = tid >> 2, c_ = tid & 3;
    auto issue = [&](int t, int s) {
        uint32_t dA = sb + (s * 5120 + r_ * 20 + c_ * 4) * 4;
        uint32_t dB = dA + 2560 * 4;
        const half_t* as = Ag + t * 32;
        const half_t* bs = Bg + t * 32;
        cpa16(dA,            as + (size_t)r_ * lda + c_ * 8);
        cpa16(dA + 64 * 80,  as + (size_t)(r_ + 64) * lda + c_ * 8);
        cpa16(dB,            bs + (size_t)r_ * ldb + c_ * 8);
        cpa16(dB + 64 * 80,  bs + (size_t)(r_ + 64) * ldb + c_ * 8);
        CPA_COMMIT();
    };
    auto compute = [&](int s) {
        const uint32_t base  = sb + s * 5120 * 4;
        const uint32_t aBase = base + (m_off + row16) * 80 + half_ * 16;
        const uint32_t bBase = base + 2560 * 4 + (n_off + row16) * 80 + half_ * 16;
        #pragma unroll
        for (int ks = 0; ks < 2; ++ks) {
            uint32_t af[4][4], bq[2][4];
            #pragma unroll
            for (int mt = 0; mt < 4; ++mt) ldsm4(af[mt], aBase + mt * 1280 + ks * 32);
            #pragma unroll
            for (int p = 0; p < 2; ++p)    ldsm4(bq[p], bBase + p * 1280 + ks * 32);
            #pragma unroll
            for (int mt = 0; mt < 4; ++mt)
                #pragma unroll
                for (int nt = 0; nt < 4; ++nt) {
                    uint32_t bfr[2] = { bq[nt >> 1][nt & 1], bq[nt >> 1][(nt & 1) + 2] };
                    mma16(acc[mt][nt], af[mt], bfr);
                }
        }
    };

    const int ntl = K / 32;
    issue(0, 0);
    if (ntl > 1) issue(1, 1);
    if (ntl > 2) issue(2, 2);
    for (int t = 0; t < ntl; ++t) {
        const int rem = ntl - 1 - t;
        if (rem >= 2)      asm volatile("cp.async.wait_group 2;" ::: "memory");
        else if (rem == 1) asm volatile("cp.async.wait_group 1;" ::: "memory");
        else               asm volatile("cp.async.wait_group 0;" ::: "memory");
        __syncthreads();
        if (t + 3 < ntl) issue(t + 3, (t + 3) & 3);
        compute(t & 3);
    }

    // ---------------- epilogue: direct normal store ----------------
    #pragma unroll
    for (int mt = 0; mt < 4; ++mt) {
        const int rml = m_off + mt * 16 + g;
        float rb0 = 0.f, rb1 = 0.f;
        if (!BIASCOL && bias) { rb0 = bias[m0 + rml]; rb1 = bias[m0 + rml + 8]; }
        #pragma unroll
        for (int nt = 0; nt < 4; ++nt) {
            const int col = n0 + n_off + nt * 8 + 2 * tig;
            float2 cb = make_float2(0.f, 0.f);
            if (BIASCOL && bias) cb = *reinterpret_cast<const float2*>(bias + col);
            float v0x = alpha * acc[mt][nt][0], v0y = alpha * acc[mt][nt][1];
            float v1x = alpha * acc[mt][nt][2], v1y = alpha * acc[mt][nt][3];
            if (BIASCOL) { v0x += cb.x; v0y += cb.y; v1x += cb.x; v1y += cb.y; }
            else         { v0x += rb0;  v0y += rb0;  v1x += rb1;  v1y += rb1;  }
            size_t i0 = (size_t)(m0 + rml)     * ldd + col;
            size_t i1 = (size_t)(m0 + rml + 8) * ldd + col;
            if (OUTF32) {
                float* dst = (float*)D + sD * (size_t)z;
                if (res) {
                    const float* rp = res + sR * (size_t)z;
                    float2 r0 = *reinterpret_cast<const float2*>(rp + i0);
                    float2 r1 = *reinterpret_cast<const float2*>(rp + i1);
                    v0x += r0.x; v0y += r0.y; v1x += r1.x; v1y += r1.y;
                }
                *reinterpret_cast<float2*>(dst + i0) = make_float2(v0x, v0y);
                *reinterpret_cast<float2*>(dst + i1) = make_float2(v1x, v1y);
            } else {
                half_t* dst = (half_t*)D + sD * (size_t)z;
                *reinterpret_cast<__half2*>(dst + i0) = __float22half2_rn(make_float2(v0x, v0y));
                *reinterpret_cast<__half2*>(dst + i1) = __float22half2_rn(make_float2(v1x, v1y));
            }
        }
    }
}

// ---------------- fp32 -> fp16 weight convert -------------------------------
__global__ void cvt_kernel(const float* __restrict__ src, half_t* __restrict__ dst, int n4) {
    int i = blockIdx.x * 256 + threadIdx.x;
    if (i < n4) {
        float4 v = reinterpret_cast<const float4*>(src)[i];
        __half2 a = __float22half2_rn(make_float2(v.x, v.y));
        __half2 b = __float22half2_rn(make_float2(v.z, v.w));
        reinterpret_cast<uint2*>(dst)[i] = make_uint2(
            *reinterpret_cast<uint32_t*>(&a), *reinterpret_cast<uint32_t*>(&b));
    }
}

// ---------------- GroupNorm pass 1 ------------------------------------------
__global__ __launch_bounds__(256) void gn_stats(const float* __restrict__ x,
                                                const float* __restrict__ w,
                                                const float* __restrict__ bb,
                                                float* __restrict__ sc,
                                                float* __restrict__ sh) {
    const int bg = blockIdx.x;
    const int bi = bg >> 5;
    const int g  = bg & 31;
    const size_t base = ((size_t)bi * C_ + (size_t)g * CPG) * T_;
    const float4* xp4 = reinterpret_cast<const float4*>(x + base);
    const int n4 = CPG * T_ / 4;
    float s = 0.f, s2 = 0.f;
    for (int i = threadIdx.x; i < n4; i += 256) {
        float4 v = xp4[i];
        s  += v.x + v.y + v.z + v.w;
        s2 += v.x * v.x + v.y * v.y + v.z * v.z + v.w * v.w;
    }
    __shared__ float rs[256], rq[256];
    rs[threadIdx.x] = s; rq[threadIdx.x] = s2;
    __syncthreads();
    for (int off = 128; off > 0; off >>= 1) {
        if (threadIdx.x < off) {
            rs[threadIdx.x] += rs[threadIdx.x + off];
            rq[threadIdx.x] += rq[threadIdx.x + off];
        }
        __syncthreads();
    }
    const float inv_n = 1.0f / (float)(CPG * T_);
    const float mean  = rs[0] * inv_n;
    const float var   = rq[0] * inv_n - mean * mean;
    const float rstd  = rsqrtf(var + 1e-5f);
    if (threadIdx.x < CPG) {
        int c = g * CPG + threadIdx.x;
        float scv = w[c] * rstd;
        sc[bi * C_ + c] = scv;
        sh[bi * C_ + c] = bb[c] - mean * scv;
    }
}

// ---------------- GroupNorm pass 2: normalize + transpose -> fp16 hT --------
// Tiles of 64 channels x 128 t; 32KB static smem (f32 staged), high occupancy.
__global__ __launch_bounds__(256) void gn_tr(const float* __restrict__ x,
                                             const float* __restrict__ sc,
                                             const float* __restrict__ sh,
                                             half_t* __restrict__ hT) {
    __shared__ float smf[64 * 128];
    const int t0 = blockIdx.x * 128, c0 = blockIdx.y * 64, z = blockIdx.z;
    const int tid = threadIdx.x;
    #pragma unroll 2
    for (int i = 0; i < 8; ++i) {
        int q = tid + 256 * i;
        int row = q >> 5, t4 = q & 31;           // row = local c (0..63)
        int c = c0 + row;
        float scv = sc[z * C_ + c], shv = sh[z * C_ + c];
        float4 v = *reinterpret_cast<const float4*>(
            x + ((size_t)z * C_ + c) * T_ + t0 + 4 * t4);
        v.x = v.x * scv + shv; v.y = v.y * scv + shv;
        v.z = v.z * scv + shv; v.w = v.w * scv + shv;
        *reinterpret_cast<float4*>(smf + 4 * slot4(row, t4)) = v;
    }
    __syncthreads();
    #pragma unroll 2
    for (int i = 0; i < 8; ++i) {
        int oq = tid + 256 * i;
        int t = oq >> 4, c4 = oq & 15;           // 4 channels per item
        float4 v;
        v.x = smf[4 * slot4(4 * c4 + 0, t >> 2) + (t & 3)];
        v.y = smf[4 * slot4(4 * c4 + 1, t >> 2) + (t & 3)];
        v.z = smf[4 * slot4(4 * c4 + 2, t >> 2) + (t & 3)];
        v.w = smf[4 * slot4(4 * c4 + 3, t >> 2) + (t & 3)];
        __half2 a = __float22half2_rn(make_float2(v.x, v.y));
        __half2 b = __float22half2_rn(make_float2(v.z, v.w));
        *reinterpret_cast<uint2*>(hT + ((size_t)z * T_ + t0 + t) * C_ + c0 + 4 * c4) =
            make_uint2(*reinterpret_cast<uint32_t*>(&a), *reinterpret_cast<uint32_t*>(&b));
    }
}

// ---------------- Row softmax: fp16 in-place (f32 math) ---------------------
__global__ __launch_bounds__(256) void softmax_kernel(half_t* __restrict__ s) {
    uint4* p = reinterpret_cast<uint4*>(s + (size_t)blockIdx.x * T_);  // 512 uint4/row
    const int tid = threadIdx.x;
    uint4 u[2];
    float f[2][8];
    float mx = -1e30f;
    #pragma unroll
    for (int r = 0; r < 2; ++r) {
        u[r] = p[tid + 256 * r];
        const __half2* hp = reinterpret_cast<const __half2*>(&u[r]);
        #pragma unroll
        for (int j = 0; j < 4; ++j) {
            float2 a = __half22float2(hp[j]);
            f[r][2 * j] = a.x; f[r][2 * j + 1] = a.y;
            mx = fmaxf(mx, fmaxf(a.x, a.y));
        }
    }
    __shared__ float red[256];
    red[tid] = mx;
    __syncthreads();
    for (int off = 128; off > 0; off >>= 1) {
        if (tid < off) red[tid] = fmaxf(red[tid], red[tid + off]);
        __syncthreads();
    }
    mx = red[0];
    __syncthreads();
    float sum = 0.f;
    #pragma unroll
    for (int r = 0; r < 2; ++r)
        #pragma unroll
        for (int j = 0; j < 8; ++j) {
            f[r][j] = __expf(f[r][j] - mx);
            sum += f[r][j];
        }
    red[tid] = sum;
    __syncthreads();
    for (int off = 128; off > 0; off >>= 1) {
        if (tid < off) red[tid] += red[tid + off];
        __syncthreads();
    }
    const float inv = 1.0f / red[0];
    #pragma unroll
    for (int r = 0; r < 2; ++r) {
        __half2* hp = reinterpret_cast<__half2*>(&u[r]);
        #pragma unroll
        for (int j = 0; j < 4; ++j)
            hp[j] = __float22half2_rn(make_float2(f[r][2 * j] * inv, f[r][2 * j + 1] * inv));
        p[tid + 256 * r] = u[r];
    }
}

// ---------------------------------------------------------------------------
extern "C" void kernel_launch(void* const* d_in, const int* in_sizes, int n_in,
                              void* d_out, int out_size) {
    const float* x      = (const float*)d_in[0];
    const float* gn_w   = (const float*)d_in[1];
    const float* gn_b   = (const float*)d_in[2];
    const float* qkv_w  = (const float*)d_in[3];
    const float* qkv_b  = (const float*)d_in[4];
    const float* proj_w = (const float*)d_in[5];
    const float* proj_b = (const float*)d_in[6];
    float* out = (float*)d_out;

    half_t *hT, *qkT, *v, *s, *aoT, *wq, *wp;
    float *sc, *sh;
    cudaGetSymbolAddress((void**)&hT,  g_hT);
    cudaGetSymbolAddress((void**)&qkT, g_qkT);
    cudaGetSymbolAddress((void**)&v,   g_v);
    cudaGetSymbolAddress((void**)&s,   g_s);
    cudaGetSymbolAddress((void**)&aoT, g_aoT);
    cudaGetSymbolAddress((void**)&wq,  g_wq);
    cudaGetSymbolAddress((void**)&wp,  g_wp);
    cudaGetSymbolAddress((void**)&sc,  g_sc);
    cudaGetSymbolAddress((void**)&sh,  g_sh);

    const int GSM = 4 * 5120 * 4;   // 80 KB
    cudaFuncSetAttribute(gemm_f16<false, true>,  cudaFuncAttributeMaxDynamicSharedMemorySize, GSM);
    cudaFuncSetAttribute(gemm_f16<false, false>, cudaFuncAttributeMaxDynamicSharedMemorySize, GSM);
    cudaFuncSetAttribute(gemm_f16<true,  false>, cudaFuncAttributeMaxDynamicSharedMemorySize, GSM);

    const size_t CT  = (size_t)C_ * T_;
    const size_t TT  = (size_t)T_ * T_;
    const size_t TC  = (size_t)T_ * C_;
    const size_t T2C = (size_t)T_ * 2 * C_;

    // 0) weight conversion fp32 -> fp16
    cvt_kernel<<<(3 * C_ * C_ / 4 + 255) / 256, 256>>>(qkv_w, wq, 3 * C_ * C_ / 4);
    cvt_kernel<<<(C_ * C_ / 4 + 255) / 256, 256>>>(proj_w, wp, C_ * C_ / 4);

    // 1) GroupNorm
    gn_stats<<<B_ * G_, 256>>>(x, gn_w, gn_b, sc, sh);
    gn_tr<<<dim3(T_ / 128, C_ / 64, B_), 256>>>(x, sc, sh, hT);

    // 2a) QK: D[t,o] = hT[t,:].W[o,:] + b[o] (col bias) -> qkT[t][o], o<1024
    gemm_f16<false, true><<<dim3(1024 / 128, T_ / 128, B_), 256, GSM>>>(
        hT, wq, qkT, qkv_b, nullptr,
        C_, C_, C_, 2 * C_,
        TC, 0, T2C, 0, 1.0f);

    // 2b) V: D[c,t] = Wv[c,:].hT[t,:] + b (row bias) -> v[c][t]
    gemm_f16<false, false><<<dim3(T_ / 128, C_ / 128, B_), 256, GSM>>>(
        wq + 2 * C_ * C_, hT, v, qkv_b + 2 * C_, nullptr,
        C_, C_, C_, T_,
        0, TC, CT, 0, 1.0f);

    // 3) Scores: S[t,n] = alpha * q[t,:].k[n,:]  (fp16 store)
    gemm_f16<false, false><<<dim3(T_ / 128, T_ / 128, B_), 256, GSM>>>(
        qkT, qkT + C_, s, nullptr, nullptr,
        C_, 2 * C_, 2 * C_, T_,
        T2C, T2C, TT, 0, 0.04419417382415922f);

    // 4) Softmax in-place fp16
    softmax_kernel<<<B_ * T_, 256>>>(s);

    // 5) AV: D[t,c] = attn[t,:].v[c,:] -> aoT[t][c]
    gemm_f16<false, false><<<dim3(C_ / 128, T_ / 128, B_), 256, GSM>>>(
        s, v, aoT, nullptr, nullptr,
        T_, T_, T_, C_,
        TT, CT, TC, 0, 1.0f);

    // 6) Proj: out[c,t] = Wp[c,:].aoT[t,:] + pb[c] + x  (f32)
    gemm_f16<true, false><<<dim3(T_ / 128, C_ / 128, B_), 256, GSM>>>(
        wp, aoT, out, proj_b, x,
        C_, C_, C_, T_,
        0, TC, CT, CT, 1.0f);
}